// round 4
// baseline (speedup 1.0000x reference)
#include <cuda_runtime.h>
#include <cuda_fp16.h>
#include <mma.h>
#include <cstdint>

using namespace nvcuda;

#define NE 16
#define NT 2048
#define DD 1024
#define HH 4096

// ---------------- scratch (allocation-free rule: __device__ globals) --------
__device__ __half g_xh [(size_t)NE * NT * DD];   // x  fp16, [E][N][D]
__device__ __half g_w1t[(size_t)NE * HH * DD];   // w1 fp16, [E][H][D] (K-major)
__device__ __half g_w2t[(size_t)NE * DD * HH];   // w2 fp16, [E][D][H] (K-major)
__device__ __half g_hid[(size_t)NE * NT * HH];   // hidden fp16, [E][N][H]

// ---------------- GEMM config ----------------------------------------------
constexpr int BM = 128, BN = 128, BK = 64;
constexpr int SST    = 72;                 // smem stride (halfs): 64 data + 8 pad
constexpr int ROWB   = SST * 2;            // 144 B per row
constexpr int TILE_B = 128 * ROWB;         // 18432 B per operand tile
constexpr int STG    = 2 * TILE_B;         // 36864 B per stage (A + B)
constexpr int NSTAGE = 3;                  // 110592 B -> 2 CTAs/SM
constexpr int SMEM_GEMM = NSTAGE * STG + 1024;

#define CPA(dst, src) asm volatile("cp.async.cg.shared.global [%0], [%1], 16;" :: "r"(dst), "l"(src))
#define CPC()         asm volatile("cp.async.commit_group;" ::: "memory")
#define CPW(n)        asm volatile("cp.async.wait_group %0;" :: "n"(n) : "memory")

__device__ __forceinline__ float gelu_exact(float v) {
    return 0.5f * v * (1.0f + erff(v * 0.70710678118654752440f));
}

// ---------------------------------------------------------------------------
// C[MxN] = A[MxK] @ Bt[NxK]^T   (both operands fp16 K-major, fp32 accum)
// MODE 1: Oh = fp16(gelu(C + bias))     MODE 2: Of = C + bias (fp32)
// ---------------------------------------------------------------------------
template <int MODE>
__global__ void __launch_bounds__(256, 2) gemm_ffn(
    const __half* __restrict__ A, const __half* __restrict__ Bt,
    const float* __restrict__ bias,
    __half* __restrict__ Oh, float* __restrict__ Of,
    int M, int Ntot, int K)
{
    extern __shared__ char smem[];
    const uint32_t sb = (uint32_t)__cvta_generic_to_shared(smem);

    const int tid  = threadIdx.x;
    const int warp = tid >> 5;
    const int wm   = warp >> 1;            // 0..3 -> 32-row slices
    const int wn   = warp & 1;             // 0..1 -> 64-col slices

    const int e  = blockIdx.z;
    const int m0 = blockIdx.y * BM;
    const int n0 = blockIdx.x * BN;

    const __half* Ae = A  + ((size_t)e * M    + m0) * (size_t)K;
    const __half* Be = Bt + ((size_t)e * Ntot + n0) * (size_t)K;

    float* sBias = (float*)(smem + NSTAGE * STG);
    if (tid < 128) sBias[tid] = bias[n0 + tid];

    // cp.async addressing: 8 chunks/row (BK=64), thread covers rows r0+32j
    const int r0 = tid >> 3;               // 0..31
    const int c  = tid & 7;                // 0..7 -> 16B chunk
    const __half* gA = Ae + (size_t)r0 * K + c * 8;
    const __half* gB = Be + (size_t)r0 * K + c * 8;
    const uint32_t sd0 = sb + r0 * ROWB + c * 16;

    const int NIT = K / BK;

    // prologue: stages 0..NSTAGE-2
    #pragma unroll
    for (int s = 0; s < NSTAGE - 1; s++) {
        const uint32_t sd = sd0 + s * STG;
        const int k0 = s * BK;
        #pragma unroll
        for (int j = 0; j < 4; j++) {
            CPA(sd + j * 32 * ROWB,              gA + k0 + (size_t)(j * 32) * K);
            CPA(sd + TILE_B + j * 32 * ROWB,     gB + k0 + (size_t)(j * 32) * K);
        }
        CPC();
    }

    wmma::fragment<wmma::accumulator, 16, 16, 16, float> acc[2][4];
    #pragma unroll
    for (int mi = 0; mi < 2; mi++)
        #pragma unroll
        for (int ni = 0; ni < 4; ni++) wmma::fill_fragment(acc[mi][ni], 0.0f);

    int cur = 0;
    for (int i = 0; i < NIT; i++) {
        CPW(1);
        __syncthreads();

        if (i + NSTAGE - 1 < NIT) {
            const uint32_t sd = sd0 + ((i + NSTAGE - 1) % NSTAGE) * STG;
            const size_t   k0 = (size_t)(i + NSTAGE - 1) * BK;
            #pragma unroll
            for (int j = 0; j < 4; j++) {
                CPA(sd + j * 32 * ROWB,          gA + k0 + (size_t)(j * 32) * K);
                CPA(sd + TILE_B + j * 32 * ROWB, gB + k0 + (size_t)(j * 32) * K);
            }
        }
        CPC();   // empty groups in the tail keep wait_group semantics exact

        const __half* As = (const __half*)(smem + cur * STG);
        const __half* Bs = As + 128 * SST;
        cur = (cur + 1 == NSTAGE) ? 0 : cur + 1;

        #pragma unroll
        for (int kk = 0; kk < 4; kk++) {
            wmma::fragment<wmma::matrix_a, 16, 16, 16, __half, wmma::row_major> af[2];
            wmma::fragment<wmma::matrix_b, 16, 16, 16, __half, wmma::col_major> bf[4];
            #pragma unroll
            for (int mi = 0; mi < 2; mi++)
                wmma::load_matrix_sync(af[mi], As + (wm * 32 + mi * 16) * SST + kk * 16, SST);
            #pragma unroll
            for (int ni = 0; ni < 4; ni++)
                wmma::load_matrix_sync(bf[ni], Bs + (wn * 64 + ni * 16) * SST + kk * 16, SST);
            #pragma unroll
            for (int mi = 0; mi < 2; mi++)
                #pragma unroll
                for (int ni = 0; ni < 4; ni++)
                    wmma::mma_sync(acc[mi][ni], af[mi], bf[ni], acc[mi][ni]);
        }
    }

    // ---- epilogue: accum -> smem -> (bias[+gelu]) -> global
    __syncthreads();
    float* eb = (float*)smem;              // 128 x 132 fp32 = 67.6 KB (fits)
    #pragma unroll
    for (int mi = 0; mi < 2; mi++)
        #pragma unroll
        for (int ni = 0; ni < 4; ni++)
            wmma::store_matrix_sync(eb + (wm * 32 + mi * 16) * 132 + wn * 64 + ni * 16,
                                    acc[mi][ni], 132, wmma::mem_row_major);
    __syncthreads();

    const int row = tid >> 1;
    const int cb  = (tid & 1) * 64;
    const size_t gbase = ((size_t)e * M + m0 + row) * (size_t)Ntot + n0 + cb;

    #pragma unroll
    for (int cc = 0; cc < 64; cc += 8) {
        float v[8];
        #pragma unroll
        for (int q = 0; q < 8; q++)
            v[q] = eb[row * 132 + cb + cc + q] + sBias[cb + cc + q];
        if (MODE == 1) {
            __align__(16) __half hv[8];
            #pragma unroll
            for (int q = 0; q < 8; q++) hv[q] = __float2half(gelu_exact(v[q]));
            *(uint4*)(Oh + gbase + cc) = *(const uint4*)hv;
        } else {
            *(float4*)(Of + gbase + cc)     = make_float4(v[0], v[1], v[2], v[3]);
            *(float4*)(Of + gbase + cc + 4) = make_float4(v[4], v[5], v[6], v[7]);
        }
    }
}

// ---------------- preprocessing ---------------------------------------------
__global__ void __launch_bounds__(256) f2h_kernel(
    const float* __restrict__ x, __half* __restrict__ o, size_t n4)
{
    size_t i = (size_t)blockIdx.x * 256 + threadIdx.x;
    if (i >= n4) return;
    float4 v = ((const float4*)x)[i];
    __half2 h0 = __floats2half2_rn(v.x, v.y);
    __half2 h1 = __floats2half2_rn(v.z, v.w);
    ((__half2*)o)[2 * i]     = h0;
    ((__half2*)o)[2 * i + 1] = h1;
}

// w [E][K][N] fp32 -> o [E][N][K] fp16
__global__ void __launch_bounds__(256) trans_h_kernel(
    const float* __restrict__ w, __half* __restrict__ o, int K, int N)
{
    __shared__ float t[32][33];
    const int e  = blockIdx.z;
    const int k0 = blockIdx.y * 32;
    const int n0 = blockIdx.x * 32;
    const int tx = threadIdx.x & 31;
    const int ty = threadIdx.x >> 5;   // 0..7
    const float* s = w + (size_t)e * K * N;
    #pragma unroll
    for (int i = 0; i < 4; i++)
        t[ty + 8 * i][tx] = s[(size_t)(k0 + ty + 8 * i) * N + n0 + tx];
    __syncthreads();
    __half* d = o + (size_t)e * N * K;
    #pragma unroll
    for (int i = 0; i < 4; i++)
        d[(size_t)(n0 + ty + 8 * i) * K + k0 + tx] = __float2half(t[tx][ty + 8 * i]);
}

// ---------------- launch -----------------------------------------------------
extern "C" void kernel_launch(void* const* d_in, const int* in_sizes, int n_in,
                              void* d_out, int out_size)
{
    const float* x  = (const float*)d_in[0];
    const float* w1 = (const float*)d_in[1];
    const float* w2 = (const float*)d_in[2];
    const float* b1 = (const float*)d_in[3];
    const float* b2 = (const float*)d_in[4];
    float* out = (float*)d_out;

    __half *xh, *w1t, *w2t, *hid;
    cudaGetSymbolAddress((void**)&xh,  g_xh);
    cudaGetSymbolAddress((void**)&w1t, g_w1t);
    cudaGetSymbolAddress((void**)&w2t, g_w2t);
    cudaGetSymbolAddress((void**)&hid, g_hid);

    cudaFuncSetAttribute(gemm_ffn<1>, cudaFuncAttributeMaxDynamicSharedMemorySize, SMEM_GEMM);
    cudaFuncSetAttribute(gemm_ffn<2>, cudaFuncAttributeMaxDynamicSharedMemorySize, SMEM_GEMM);

    // 1) x -> fp16
    size_t n4 = (size_t)NE * NT * DD / 4;
    f2h_kernel<<<(unsigned)((n4 + 255) / 256), 256>>>(x, xh, n4);

    // 2) weights -> K-major fp16
    dim3 t1(HH / 32, DD / 32, NE);
    trans_h_kernel<<<t1, 256>>>(w1, w1t, DD, HH);
    dim3 t2(DD / 32, HH / 32, NE);
    trans_h_kernel<<<t2, 256>>>(w2, w2t, HH, DD);

    // 3) GEMM1: hidden = gelu(x @ w1 + b1)   (fp16 out)
    dim3 g1(HH / BN, NT / BM, NE);
    gemm_ffn<1><<<g1, 256, SMEM_GEMM>>>(xh, w1t, b1, hid, nullptr, NT, HH, DD);

    // 4) GEMM2: out = hidden @ w2 + b2       (fp32 out)
    dim3 g2(DD / BN, NT / BM, NE);
    gemm_ffn<2><<<g2, 256, SMEM_GEMM>>>(hid, w2t, b2, nullptr, out, NT, DD, HH);
}

// round 7
// speedup vs baseline: 1.3889x; 1.3889x over previous
#include <cuda_runtime.h>
#include <cuda_fp16.h>
#include <mma.h>
#include <cstdint>

using namespace nvcuda;

#define NE 16
#define NT 2048
#define DD 1024
#define HH 4096

// ---------------- scratch (allocation-free rule: __device__ globals) --------
__device__ __half g_xh [(size_t)NE * NT * DD];   // x  fp16, [E][N][D]
__device__ __half g_w1t[(size_t)NE * HH * DD];   // w1 fp16, [E][H][D] (K-major)
__device__ __half g_w2t[(size_t)NE * DD * HH];   // w2 fp16, [E][D][H] (K-major)
__device__ __half g_hid[(size_t)NE * NT * HH];   // hidden fp16, [E][N][H]

// ---------------- GEMM config ----------------------------------------------
constexpr int BM = 128, BN = 256, BK = 64;
constexpr int NTH  = 512;                  // 16 warps, one CTA per SM
constexpr int SST  = 72;                   // smem stride (halfs): 64 data + 8 pad
constexpr int ROWB = SST * 2;              // 144 B per row
constexpr int TROWS = BM + BN;             // 384 rows per stage (A then B)
constexpr int TILE_A = BM * ROWB;          // 18432 B
constexpr int STG    = TROWS * ROWB;       // 55296 B per stage
constexpr int NSTAGE = 3;
constexpr int SMEM_GEMM = NSTAGE * STG + 1024;   // ~167 KB

#define CPA(dst, src) asm volatile("cp.async.cg.shared.global [%0], [%1], 16;" :: "r"(dst), "l"(src))
#define CPC()         asm volatile("cp.async.commit_group;" ::: "memory")
#define CPW(n)        asm volatile("cp.async.wait_group %0;" :: "n"(n) : "memory")

__device__ __forceinline__ float gelu_exact(float v) {
    return 0.5f * v * (1.0f + erff(v * 0.70710678118654752440f));
}

// ---------------------------------------------------------------------------
// C[MxN] = A[MxK] @ Bt[NxK]^T   (fp16 K-major operands, fp32 accum)
// MODE 1: Oh = fp16(gelu(C + bias))     MODE 2: Of = C + bias (fp32)
// ---------------------------------------------------------------------------
template <int MODE>
__global__ void __launch_bounds__(NTH, 1) gemm_ffn(
    const __half* __restrict__ A, const __half* __restrict__ Bt,
    const float* __restrict__ bias,
    __half* __restrict__ Oh, float* __restrict__ Of,
    int M, int Ntot, int K)
{
    extern __shared__ char smem[];
    const uint32_t sb = (uint32_t)__cvta_generic_to_shared(smem);

    const int tid  = threadIdx.x;
    const int warp = tid >> 5;
    const int wm   = warp >> 2;            // 0..3 -> 32-row slices
    const int wn   = warp & 3;             // 0..3 -> 64-col slices

    const int e  = blockIdx.z;
    const int m0 = blockIdx.y * BM;
    const int n0 = blockIdx.x * BN;

    const __half* Ae = A  + ((size_t)e * M    + m0) * (size_t)K;
    const __half* Be = Bt + ((size_t)e * Ntot + n0) * (size_t)K;

    float* sBias = (float*)(smem + NSTAGE * STG);
    if (tid < 256) sBias[tid] = bias[n0 + tid];

    // cp.async: 384 rows x 8 chunks = 3072 slots, 6 per thread
    const int r0 = tid >> 3;               // 0..63
    const int c  = tid & 7;                // 16B chunk
    const __half* gA = Ae + (size_t)r0 * K + c * 8;
    const __half* gB = Be + (size_t)r0 * K + c * 8;
    const uint32_t sd0 = sb + r0 * ROWB + c * 16;

    const int NIT = K / BK;

    // prologue: stages 0..NSTAGE-2
    #pragma unroll
    for (int s = 0; s < NSTAGE - 1; s++) {
        const uint32_t sd = sd0 + s * STG;
        const int k0 = s * BK;
        CPA(sd,                    gA + k0);
        CPA(sd + 64 * ROWB,        gA + k0 + (size_t)64 * K);
        #pragma unroll
        for (int j = 0; j < 4; j++)
            CPA(sd + TILE_A + j * 64 * ROWB, gB + k0 + (size_t)(j * 64) * K);
        CPC();
    }

    wmma::fragment<wmma::accumulator, 16, 16, 16, float> acc[2][4];
    #pragma unroll
    for (int mi = 0; mi < 2; mi++)
        #pragma unroll
        for (int ni = 0; ni < 4; ni++) wmma::fill_fragment(acc[mi][ni], 0.0f);

    int cur = 0;
    for (int i = 0; i < NIT; i++) {
        CPW(1);
        __syncthreads();

        if (i + NSTAGE - 1 < NIT) {
            const uint32_t sd = sd0 + ((i + NSTAGE - 1) % NSTAGE) * STG;
            const size_t   k0 = (size_t)(i + NSTAGE - 1) * BK;
            CPA(sd,             gA + k0);
            CPA(sd + 64 * ROWB, gA + k0 + (size_t)64 * K);
            #pragma unroll
            for (int j = 0; j < 4; j++)
                CPA(sd + TILE_A + j * 64 * ROWB, gB + k0 + (size_t)(j * 64) * K);
        }
        CPC();   // empty groups in the tail keep wait_group semantics exact

        const __half* As = (const __half*)(smem + cur * STG);
        const __half* Bs = As + BM * SST;
        cur = (cur + 1 == NSTAGE) ? 0 : cur + 1;

        #pragma unroll
        for (int kk = 0; kk < 4; kk++) {
            wmma::fragment<wmma::matrix_a, 16, 16, 16, __half, wmma::row_major> af[2];
            wmma::fragment<wmma::matrix_b, 16, 16, 16, __half, wmma::col_major> bf[4];
            #pragma unroll
            for (int mi = 0; mi < 2; mi++)
                wmma::load_matrix_sync(af[mi], As + (wm * 32 + mi * 16) * SST + kk * 16, SST);
            #pragma unroll
            for (int ni = 0; ni < 4; ni++)
                wmma::load_matrix_sync(bf[ni], Bs + (wn * 64 + ni * 16) * SST + kk * 16, SST);
            #pragma unroll
            for (int mi = 0; mi < 2; mi++)
                #pragma unroll
                for (int ni = 0; ni < 4; ni++)
                    wmma::mma_sync(acc[mi][ni], af[mi], bf[ni], acc[mi][ni]);
        }
    }

    // ---- epilogue: accum -> smem -> (bias[+gelu]) -> global
    __syncthreads();
    float* eb = (float*)smem;              // 128 x 260 fp32 = 133 KB (fits in 167 KB)
    #pragma unroll
    for (int mi = 0; mi < 2; mi++)
        #pragma unroll
        for (int ni = 0; ni < 4; ni++)
            wmma::store_matrix_sync(eb + (wm * 32 + mi * 16) * 260 + wn * 64 + ni * 16,
                                    acc[mi][ni], 260, wmma::mem_row_major);
    __syncthreads();

    const int row = tid >> 2;              // 0..127
    const int cb  = (tid & 3) * 64;
    const size_t gbase = ((size_t)e * M + m0 + row) * (size_t)Ntot + n0 + cb;

    #pragma unroll
    for (int cc = 0; cc < 64; cc += 8) {
        float v[8];
        #pragma unroll
        for (int q = 0; q < 8; q++)
            v[q] = eb[row * 260 + cb + cc + q] + sBias[cb + cc + q];
        if (MODE == 1) {
            __align__(16) __half hv[8];
            #pragma unroll
            for (int q = 0; q < 8; q++) hv[q] = __float2half(gelu_exact(v[q]));
            *(uint4*)(Oh + gbase + cc) = *(const uint4*)hv;
        } else {
            *(float4*)(Of + gbase + cc)     = make_float4(v[0], v[1], v[2], v[3]);
            *(float4*)(Of + gbase + cc + 4) = make_float4(v[4], v[5], v[6], v[7]);
        }
    }
}

// ---------------- preprocessing ---------------------------------------------
__global__ void __launch_bounds__(256) f2h_kernel(
    const float* __restrict__ x, __half* __restrict__ o, size_t n4)
{
    size_t i = (size_t)blockIdx.x * 256 + threadIdx.x;
    if (i >= n4) return;
    float4 v = ((const float4*)x)[i];
    __half2 h0 = __floats2half2_rn(v.x, v.y);
    __half2 h1 = __floats2half2_rn(v.z, v.w);
    ((__half2*)o)[2 * i]     = h0;
    ((__half2*)o)[2 * i + 1] = h1;
}

// w [E][K][N] fp32 -> o [E][N][K] fp16
__global__ void __launch_bounds__(256) trans_h_kernel(
    const float* __restrict__ w, __half* __restrict__ o, int K, int N)
{
    __shared__ float t[32][33];
    const int e  = blockIdx.z;
    const int k0 = blockIdx.y * 32;
    const int n0 = blockIdx.x * 32;
    const int tx = threadIdx.x & 31;
    const int ty = threadIdx.x >> 5;   // 0..7
    const float* s = w + (size_t)e * K * N;
    #pragma unroll
    for (int i = 0; i < 4; i++)
        t[ty + 8 * i][tx] = s[(size_t)(k0 + ty + 8 * i) * N + n0 + tx];
    __syncthreads();
    __half* d = o + (size_t)e * N * K;
    #pragma unroll
    for (int i = 0; i < 4; i++)
        d[(size_t)(n0 + ty + 8 * i) * K + k0 + tx] = __float2half(t[tx][ty + 8 * i]);
}

// ---------------- launch -----------------------------------------------------
extern "C" void kernel_launch(void* const* d_in, const int* in_sizes, int n_in,
                              void* d_out, int out_size)
{
    const float* x  = (const float*)d_in[0];
    const float* w1 = (const float*)d_in[1];
    const float* w2 = (const float*)d_in[2];
    const float* b1 = (const float*)d_in[3];
    const float* b2 = (const float*)d_in[4];
    float* out = (float*)d_out;

    __half *xh, *w1t, *w2t, *hid;
    cudaGetSymbolAddress((void**)&xh,  g_xh);
    cudaGetSymbolAddress((void**)&w1t, g_w1t);
    cudaGetSymbolAddress((void**)&w2t, g_w2t);
    cudaGetSymbolAddress((void**)&hid, g_hid);

    cudaFuncSetAttribute(gemm_ffn<1>, cudaFuncAttributeMaxDynamicSharedMemorySize, SMEM_GEMM);
    cudaFuncSetAttribute(gemm_ffn<2>, cudaFuncAttributeMaxDynamicSharedMemorySize, SMEM_GEMM);

    // 1) x -> fp16
    size_t n4 = (size_t)NE * NT * DD / 4;
    f2h_kernel<<<(unsigned)((n4 + 255) / 256), 256>>>(x, xh, n4);

    // 2) weights -> K-major fp16
    dim3 t1(HH / 32, DD / 32, NE);
    trans_h_kernel<<<t1, 256>>>(w1, w1t, DD, HH);
    dim3 t2(DD / 32, HH / 32, NE);
    trans_h_kernel<<<t2, 256>>>(w2, w2t, HH, DD);

    // 3) GEMM1: hidden = gelu(x @ w1 + b1)   (fp16 out)
    dim3 g1(HH / BN, NT / BM, NE);
    gemm_ffn<1><<<g1, NTH, SMEM_GEMM>>>(xh, w1t, b1, hid, nullptr, NT, HH, DD);

    // 4) GEMM2: out = hidden @ w2 + b2       (fp32 out)
    dim3 g2(DD / BN, NT / BM, NE);
    gemm_ffn<2><<<g2, NTH, SMEM_GEMM>>>(hid, w2t, b2, nullptr, out, NT, DD, HH);
}

// round 10
// speedup vs baseline: 1.5058x; 1.0842x over previous
#include <cuda_runtime.h>
#include <cuda_fp16.h>
#include <cstdint>

#define NE 16
#define NT 2048
#define DD 1024
#define HH 4096

// ---------------- scratch (allocation-free rule: __device__ globals) --------
__device__ __half g_xh [(size_t)NE * NT * DD];   // x  fp16, [E][N][D]
__device__ __half g_w1t[(size_t)NE * HH * DD];   // w1 fp16, [E][H][D] (K-major)
__device__ __half g_w2t[(size_t)NE * DD * HH];   // w2 fp16, [E][D][H] (K-major)
__device__ __half g_hid[(size_t)NE * NT * HH];   // hidden fp16, [E][N][H]

// ---------------- GEMM config ----------------------------------------------
constexpr int BM = 128, BN = 256, BK = 64;
constexpr int NTH  = 512;                  // 16 warps, one CTA per SM
constexpr int SST  = 72;                   // smem stride (halfs): 64 data + 8 pad
constexpr int ROWB = SST * 2;              // 144 B per row
constexpr int TILE_A = BM * ROWB;          // 18432 B
constexpr int STG    = (BM + BN) * ROWB;   // 55296 B per stage
constexpr int NSTAGE = 3;
constexpr int SMEM_GEMM = NSTAGE * STG + 1024;   // ~167 KB

#define CPA(dst, src) asm volatile("cp.async.cg.shared.global [%0], [%1], 16;" :: "r"(dst), "l"(src))
#define CPC()         asm volatile("cp.async.commit_group;" ::: "memory")
#define CPW(n)        asm volatile("cp.async.wait_group %0;" :: "n"(n) : "memory")

#define LDSM4(r0, r1, r2, r3, addr) \
    asm volatile("ldmatrix.sync.aligned.m8n8.x4.shared.b16 {%0,%1,%2,%3}, [%4];" \
                 : "=r"(r0), "=r"(r1), "=r"(r2), "=r"(r3) : "r"(addr))

#define MMA16816(d, a0, a1, a2, a3, b0, b1) \
    asm volatile("mma.sync.aligned.m16n8k16.row.col.f32.f16.f16.f32 " \
                 "{%0,%1,%2,%3}, {%4,%5,%6,%7}, {%8,%9}, {%0,%1,%2,%3};" \
                 : "+f"((d)[0]), "+f"((d)[1]), "+f"((d)[2]), "+f"((d)[3]) \
                 : "r"(a0), "r"(a1), "r"(a2), "r"(a3), "r"(b0), "r"(b1))

__device__ __forceinline__ float gelu_exact(float v) {
    return 0.5f * v * (1.0f + erff(v * 0.70710678118654752440f));
}

// ---------------------------------------------------------------------------
// C[MxN] = A[MxK] @ Bt[NxK]^T   (fp16 K-major operands, fp32 accum)
// MODE 1: Oh = fp16(gelu(C + bias))     MODE 2: Of = C + bias (fp32)
// ---------------------------------------------------------------------------
template <int MODE>
__global__ void __launch_bounds__(NTH, 1) gemm_ffn(
    const __half* __restrict__ A, const __half* __restrict__ Bt,
    const float* __restrict__ bias,
    __half* __restrict__ Oh, float* __restrict__ Of,
    int M, int Ntot, int K)
{
    extern __shared__ char smem[];
    const uint32_t sb = (uint32_t)__cvta_generic_to_shared(smem);

    const int tid  = threadIdx.x;
    const int warp = tid >> 5;
    const int lane = tid & 31;
    const int wm   = warp >> 2;            // 0..3 -> 32-row slice
    const int wn   = warp & 3;             // 0..3 -> 64-col slice

    const int e  = blockIdx.z;
    const int m0 = blockIdx.y * BM;
    const int n0 = blockIdx.x * BN;

    const __half* Ae = A  + ((size_t)e * M    + m0) * (size_t)K;
    const __half* Be = Bt + ((size_t)e * Ntot + n0) * (size_t)K;

    float* sBias = (float*)(smem + NSTAGE * STG);
    if (tid < 256) sBias[tid] = bias[n0 + tid];

    // cp.async: 384 rows x 8 chunks = 3072 slots, 6 per thread
    const int r0 = tid >> 3;               // 0..63
    const int ch = tid & 7;                // 16B chunk
    const __half* gA = Ae + (size_t)r0 * K + ch * 8;
    const __half* gB = Be + (size_t)r0 * K + ch * 8;
    const uint32_t sd0 = sb + r0 * ROWB + ch * 16;

    // ldmatrix lane-relative base offsets (stage-invariant)
    uint32_t aoff[2], boff[4];
    {
        const int arow = wm * 32 + (lane & 15);
        #pragma unroll
        for (int mi = 0; mi < 2; mi++)
            aoff[mi] = sb + (uint32_t)((arow + mi * 16) * ROWB + (lane >> 4) * 16);
        const int nrow = wn * 64 + ((lane >> 4) * 8) + (lane & 7);
        const int khalf = (lane >> 3) & 1;
        #pragma unroll
        for (int p = 0; p < 4; p++)
            boff[p] = sb + (uint32_t)(TILE_A + (nrow + p * 16) * ROWB + khalf * 16);
    }

    const int NIT = K / BK;

    // prologue: stages 0..NSTAGE-2
    #pragma unroll
    for (int s = 0; s < NSTAGE - 1; s++) {
        const uint32_t sd = sd0 + s * STG;
        const int k0 = s * BK;
        CPA(sd,             gA + k0);
        CPA(sd + 64 * ROWB, gA + k0 + (size_t)64 * K);
        #pragma unroll
        for (int j = 0; j < 4; j++)
            CPA(sd + TILE_A + j * 64 * ROWB, gB + k0 + (size_t)(j * 64) * K);
        CPC();
    }

    float acc[2][8][4];
    #pragma unroll
    for (int mi = 0; mi < 2; mi++)
        #pragma unroll
        for (int nj = 0; nj < 8; nj++)
            #pragma unroll
            for (int q = 0; q < 4; q++) acc[mi][nj][q] = 0.0f;

    int cur = 0;
    for (int i = 0; i < NIT; i++) {
        CPW(1);
        __syncthreads();

        if (i + NSTAGE - 1 < NIT) {
            const uint32_t sd = sd0 + ((i + NSTAGE - 1) % NSTAGE) * STG;
            const size_t   k0 = (size_t)(i + NSTAGE - 1) * BK;
            CPA(sd,             gA + k0);
            CPA(sd + 64 * ROWB, gA + k0 + (size_t)64 * K);
            #pragma unroll
            for (int j = 0; j < 4; j++)
                CPA(sd + TILE_A + j * 64 * ROWB, gB + k0 + (size_t)(j * 64) * K);
        }
        CPC();   // empty groups in the tail keep wait_group semantics exact

        const uint32_t stg = cur * STG;
        cur = (cur + 1 == NSTAGE) ? 0 : cur + 1;

        #pragma unroll
        for (int kk = 0; kk < 4; kk++) {
            const uint32_t kb = stg + kk * 32;
            uint32_t a[2][4];
            #pragma unroll
            for (int mi = 0; mi < 2; mi++)
                LDSM4(a[mi][0], a[mi][1], a[mi][2], a[mi][3], aoff[mi] + kb);
            uint32_t b[8][2];
            #pragma unroll
            for (int p = 0; p < 4; p++)
                LDSM4(b[2*p][0], b[2*p][1], b[2*p+1][0], b[2*p+1][1], boff[p] + kb);
            #pragma unroll
            for (int mi = 0; mi < 2; mi++)
                #pragma unroll
                for (int nj = 0; nj < 8; nj++)
                    MMA16816(acc[mi][nj], a[mi][0], a[mi][1], a[mi][2], a[mi][3],
                             b[nj][0], b[nj][1]);
        }
    }

    // ---- epilogue: accum -> smem -> (bias[+gelu]) -> global
    __syncthreads();
    float* eb = (float*)smem;              // 128 x 260 fp32 = 133 KB (fits)
    {
        const int er = wm * 32 + (lane >> 2);
        const int ec = wn * 64 + 2 * (lane & 3);
        #pragma unroll
        for (int mi = 0; mi < 2; mi++)
            #pragma unroll
            for (int nj = 0; nj < 8; nj++) {
                float* p0 = eb + (er + mi * 16) * 260 + ec + nj * 8;
                p0[0]   = acc[mi][nj][0];
                p0[1]   = acc[mi][nj][1];
                float* p1 = p0 + 8 * 260;
                p1[0]   = acc[mi][nj][2];
                p1[1]   = acc[mi][nj][3];
            }
    }
    __syncthreads();

    const int row = tid >> 2;              // 0..127
    const int cb  = (tid & 3) * 64;
    const size_t gbase = ((size_t)e * M + m0 + row) * (size_t)Ntot + n0 + cb;

    #pragma unroll
    for (int cc = 0; cc < 64; cc += 8) {
        float v[8];
        #pragma unroll
        for (int q = 0; q < 8; q++)
            v[q] = eb[row * 260 + cb + cc + q] + sBias[cb + cc + q];
        if (MODE == 1) {
            __align__(16) __half hv[8];
            #pragma unroll
            for (int q = 0; q < 8; q++) hv[q] = __float2half(gelu_exact(v[q]));
            *(uint4*)(Oh + gbase + cc) = *(const uint4*)hv;
        } else {
            *(float4*)(Of + gbase + cc)     = make_float4(v[0], v[1], v[2], v[3]);
            *(float4*)(Of + gbase + cc + 4) = make_float4(v[4], v[5], v[6], v[7]);
        }
    }
}

// ---------------- preprocessing ---------------------------------------------
__global__ void __launch_bounds__(256) f2h_kernel(
    const float* __restrict__ x, __half* __restrict__ o, size_t n4)
{
    size_t i = (size_t)blockIdx.x * 256 + threadIdx.x;
    if (i >= n4) return;
    float4 v = ((const float4*)x)[i];
    __half2 h0 = __floats2half2_rn(v.x, v.y);
    __half2 h1 = __floats2half2_rn(v.z, v.w);
    ((__half2*)o)[2 * i]     = h0;
    ((__half2*)o)[2 * i + 1] = h1;
}

// w [E][K][N] fp32 -> o [E][N][K] fp16
__global__ void __launch_bounds__(256) trans_h_kernel(
    const float* __restrict__ w, __half* __restrict__ o, int K, int N)
{
    __shared__ float t[32][33];
    const int e  = blockIdx.z;
    const int k0 = blockIdx.y * 32;
    const int n0 = blockIdx.x * 32;
    const int tx = threadIdx.x & 31;
    const int ty = threadIdx.x >> 5;   // 0..7
    const float* s = w + (size_t)e * K * N;
    #pragma unroll
    for (int i = 0; i < 4; i++)
        t[ty + 8 * i][tx] = s[(size_t)(k0 + ty + 8 * i) * N + n0 + tx];
    __syncthreads();
    __half* d = o + (size_t)e * N * K;
    #pragma unroll
    for (int i = 0; i < 4; i++)
        d[(size_t)(n0 + ty + 8 * i) * K + k0 + tx] = __float2half(t[tx][ty + 8 * i]);
}

// ---------------- launch -----------------------------------------------------
extern "C" void kernel_launch(void* const* d_in, const int* in_sizes, int n_in,
                              void* d_out, int out_size)
{
    const float* x  = (const float*)d_in[0];
    const float* w1 = (const float*)d_in[1];
    const float* w2 = (const float*)d_in[2];
    const float* b1 = (const float*)d_in[3];
    const float* b2 = (const float*)d_in[4];
    float* out = (float*)d_out;

    __half *xh, *w1t, *w2t, *hid;
    cudaGetSymbolAddress((void**)&xh,  g_xh);
    cudaGetSymbolAddress((void**)&w1t, g_w1t);
    cudaGetSymbolAddress((void**)&w2t, g_w2t);
    cudaGetSymbolAddress((void**)&hid, g_hid);

    cudaFuncSetAttribute(gemm_ffn<1>, cudaFuncAttributeMaxDynamicSharedMemorySize, SMEM_GEMM);
    cudaFuncSetAttribute(gemm_ffn<2>, cudaFuncAttributeMaxDynamicSharedMemorySize, SMEM_GEMM);

    // 1) x -> fp16
    size_t n4 = (size_t)NE * NT * DD / 4;
    f2h_kernel<<<(unsigned)((n4 + 255) / 256), 256>>>(x, xh, n4);

    // 2) weights -> K-major fp16
    dim3 t1(HH / 32, DD / 32, NE);
    trans_h_kernel<<<t1, 256>>>(w1, w1t, DD, HH);
    dim3 t2(DD / 32, HH / 32, NE);
    trans_h_kernel<<<t2, 256>>>(w2, w2t, HH, DD);

    // 3) GEMM1: hidden = gelu(x @ w1 + b1)   (fp16 out)
    dim3 g1(HH / BN, NT / BM, NE);
    gemm_ffn<1><<<g1, NTH, SMEM_GEMM>>>(xh, w1t, b1, hid, nullptr, NT, HH, DD);

    // 4) GEMM2: out = hidden @ w2 + b2       (fp32 out)
    dim3 g2(DD / BN, NT / BM, NE);
    gemm_ffn<2><<<g2, NTH, SMEM_GEMM>>>(hid, w2t, b2, nullptr, out, NT, DD, HH);
}